// round 1
// baseline (speedup 1.0000x reference)
#include <cuda_runtime.h>
#include <math.h>

#define BATCH 2
#define SEQ   2048
#define DIM   1024
#define HEADS 16
#define HDIM  64
#define ROWS  (BATCH * SEQ)      // 4096
#define QKVN  (3 * DIM)          // 3072
#define EPS   1e-5f
#define INV_SCALE 0.125f         // 1/sqrt(64)

// ---------------- scratch (__device__ globals: no allocation allowed) --------
__device__ float g_zn [ROWS * DIM];   // layernorm output        [4096,1024]
__device__ float g_q  [ROWS * DIM];   // [B*H, N, HD]
__device__ float g_k  [ROWS * DIM];
__device__ float g_v  [ROWS * DIM];
__device__ float g_att[ROWS * DIM];   // attention out, [4096,1024] (heads merged)

// ---------------- LayerNorm ----------------
__global__ __launch_bounds__(256) void ln_kernel(
    const float* __restrict__ z, const float* __restrict__ sc,
    const float* __restrict__ bi, float* __restrict__ out)
{
    int row = blockIdx.x;
    int t = threadIdx.x;
    const float4 v = ((const float4*)(z + row * DIM))[t];
    float s  = v.x + v.y + v.z + v.w;
    float s2 = v.x*v.x + v.y*v.y + v.z*v.z + v.w*v.w;

    __shared__ float ssum[8], ssum2[8], stats[2];
    #pragma unroll
    for (int off = 16; off > 0; off >>= 1) {
        s  += __shfl_down_sync(0xffffffffu, s,  off);
        s2 += __shfl_down_sync(0xffffffffu, s2, off);
    }
    int lane = t & 31, wid = t >> 5;
    if (lane == 0) { ssum[wid] = s; ssum2[wid] = s2; }
    __syncthreads();
    if (t == 0) {
        float a = 0.f, b = 0.f;
        #pragma unroll
        for (int i = 0; i < 8; i++) { a += ssum[i]; b += ssum2[i]; }
        float mu  = a * (1.0f / DIM);
        float var = b * (1.0f / DIM) - mu * mu;
        stats[0] = mu;
        stats[1] = rsqrtf(var + EPS);
    }
    __syncthreads();
    float mu = stats[0], rstd = stats[1];
    float4 s4 = ((const float4*)sc)[t];
    float4 b4 = ((const float4*)bi)[t];
    float4 r;
    r.x = (v.x - mu) * rstd * s4.x + b4.x;
    r.y = (v.y - mu) * rstd * s4.y + b4.y;
    r.z = (v.z - mu) * rstd * s4.z + b4.z;
    r.w = (v.w - mu) * rstd * s4.w + b4.w;
    ((float4*)(out + row * DIM))[t] = r;
}

// ---------------- SGEMM 128x128x8, 8x8 register tiles ----------------
// MODE 0: C = A @ B, scatter epilogue into g_q/g_k/g_v ([B*H,N,HD] layout)
// MODE 1: C = A @ B + bias + residual  (output projection)
template<int MODE>
__global__ __launch_bounds__(256) void sgemm_kernel(
    const float* __restrict__ A, const float* __restrict__ B,
    float* __restrict__ C, const float* __restrict__ zres,
    const float* __restrict__ bias, int M, int Ncols, int K)
{
    __shared__ float As[8][128];
    __shared__ float Bs[8][128];

    int tid = threadIdx.x;
    int bm = blockIdx.y * 128, bn = blockIdx.x * 128;
    int tx = tid & 15, ty = tid >> 4;

    int arow = tid >> 1;          // 0..127
    int acol = (tid & 1) * 4;     // 0 or 4
    int brow = tid >> 5;          // 0..7
    int bcol = (tid & 31) * 4;    // 0..124

    float acc[8][8];
    #pragma unroll
    for (int i = 0; i < 8; i++)
        #pragma unroll
        for (int j = 0; j < 8; j++) acc[i][j] = 0.f;

    for (int k0 = 0; k0 < K; k0 += 8) {
        float4 av = *(const float4*)(A + (size_t)(bm + arow) * K + k0 + acol);
        float4 bv = *(const float4*)(B + (size_t)(k0 + brow) * Ncols + bn + bcol);
        As[acol + 0][arow] = av.x;
        As[acol + 1][arow] = av.y;
        As[acol + 2][arow] = av.z;
        As[acol + 3][arow] = av.w;
        *(float4*)&Bs[brow][bcol] = bv;
        __syncthreads();

        #pragma unroll
        for (int k = 0; k < 8; k++) {
            float af[8], bf[8];
            *(float4*)(af)     = *(const float4*)&As[k][ty * 8];
            *(float4*)(af + 4) = *(const float4*)&As[k][ty * 8 + 4];
            *(float4*)(bf)     = *(const float4*)&Bs[k][tx * 8];
            *(float4*)(bf + 4) = *(const float4*)&Bs[k][tx * 8 + 4];
            #pragma unroll
            for (int i = 0; i < 8; i++)
                #pragma unroll
                for (int j = 0; j < 8; j++)
                    acc[i][j] = fmaf(af[i], bf[j], acc[i][j]);
        }
        __syncthreads();
    }

    if (MODE == 0) {
        // scatter: col n in [0,3072): h = n/192, d = (n%192)/3, which = n%3
        #pragma unroll
        for (int i = 0; i < 8; i++) {
            int gm = bm + ty * 8 + i;
            int bb = gm >> 11;           // /SEQ
            int nn = gm & (SEQ - 1);
            #pragma unroll
            for (int j = 0; j < 8; j++) {
                int gn  = bn + tx * 8 + j;
                int h   = gn / 192;
                int rem = gn - h * 192;
                int d   = rem / 3;
                int w   = rem - d * 3;
                float* dst = (w == 0) ? g_q : (w == 1) ? g_k : g_v;
                dst[(((size_t)bb * HEADS + h) * SEQ + nn) * HDIM + d] = acc[i][j];
            }
        }
    } else {
        #pragma unroll
        for (int i = 0; i < 8; i++) {
            int gm = bm + ty * 8 + i;
            #pragma unroll
            for (int j = 0; j < 8; j++) {
                int gn = bn + tx * 8 + j;
                size_t idx = (size_t)gm * Ncols + gn;
                C[idx] = acc[i][j] + bias[gn] + zres[idx];
            }
        }
    }
}

// ---------------- Flash attention (fp32, online softmax) ----------------
// grid: (N/64, B*H), 256 threads. Q tile 64x64 resident; stream K/V tiles.
#define ATTN_PAD 65
#define ATTN_SMEM_FLOATS (4 * 64 * ATTN_PAD + 3 * 64)

__global__ __launch_bounds__(256) void attn_kernel(float* __restrict__ Out)
{
    extern __shared__ float sm[];
    float* Qs   = sm;                       // [64][65]
    float* Ks   = Qs + 64 * ATTN_PAD;
    float* Vs   = Ks + 64 * ATTN_PAD;
    float* Ss   = Vs + 64 * ATTN_PAD;
    float* mrow = Ss + 64 * ATTN_PAD;
    float* lrow = mrow + 64;
    float* arow = lrow + 64;

    int tid = threadIdx.x;
    int bh  = blockIdx.y;                   // b*H + h
    int q0  = blockIdx.x * 64;
    int ty  = tid >> 4, tx = tid & 15;

    const float* Qb = g_q + ((size_t)bh * SEQ + q0) * HDIM;

    // load Q tile (coalesced float4 from global, scalar store to padded smem)
    for (int i = tid * 4; i < 64 * 64; i += 1024) {
        float4 v = *(const float4*)(Qb + i);
        int r = i >> 6, c = i & 63;
        float* p = Qs + r * ATTN_PAD + c;
        p[0] = v.x; p[1] = v.y; p[2] = v.z; p[3] = v.w;
    }
    if (tid < 64) { mrow[tid] = -1e30f; lrow[tid] = 0.f; }

    float o[4][4];
    #pragma unroll
    for (int i = 0; i < 4; i++)
        #pragma unroll
        for (int j = 0; j < 4; j++) o[i][j] = 0.f;

    for (int kt = 0; kt < SEQ / 64; kt++) {
        __syncthreads();  // protect Ks/Vs/Ss from previous iteration's readers
        const float* Kb = g_k + ((size_t)bh * SEQ + kt * 64) * HDIM;
        const float* Vb = g_v + ((size_t)bh * SEQ + kt * 64) * HDIM;
        for (int i = tid * 4; i < 64 * 64; i += 1024) {
            float4 kv = *(const float4*)(Kb + i);
            float4 vv = *(const float4*)(Vb + i);
            int r = i >> 6, c = i & 63;
            float* pk = Ks + r * ATTN_PAD + c;
            float* pv = Vs + r * ATTN_PAD + c;
            pk[0] = kv.x; pk[1] = kv.y; pk[2] = kv.z; pk[3] = kv.w;
            pv[0] = vv.x; pv[1] = vv.y; pv[2] = vv.z; pv[3] = vv.w;
        }
        __syncthreads();

        // S = Q @ K^T (64x64), 4x4 per thread
        float s[4][4];
        #pragma unroll
        for (int i = 0; i < 4; i++)
            #pragma unroll
            for (int j = 0; j < 4; j++) s[i][j] = 0.f;
        #pragma unroll 8
        for (int k = 0; k < 64; k++) {
            float a[4], b[4];
            #pragma unroll
            for (int i = 0; i < 4; i++) a[i] = Qs[(ty * 4 + i) * ATTN_PAD + k];
            #pragma unroll
            for (int j = 0; j < 4; j++) b[j] = Ks[(tx * 4 + j) * ATTN_PAD + k];
            #pragma unroll
            for (int i = 0; i < 4; i++)
                #pragma unroll
                for (int j = 0; j < 4; j++)
                    s[i][j] = fmaf(a[i], b[j], s[i][j]);
        }
        #pragma unroll
        for (int i = 0; i < 4; i++)
            #pragma unroll
            for (int j = 0; j < 4; j++)
                Ss[(ty * 4 + i) * ATTN_PAD + tx * 4 + j] = s[i][j] * INV_SCALE;
        __syncthreads();

        // online softmax per row (64 threads, one row each)
        if (tid < 64) {
            float* srow = Ss + tid * ATTN_PAD;
            float mt = srow[0];
            #pragma unroll 8
            for (int c = 1; c < 64; c++) mt = fmaxf(mt, srow[c]);
            float mo = mrow[tid];
            float mn = fmaxf(mo, mt);
            float al = __expf(mo - mn);
            float ls = 0.f;
            #pragma unroll 8
            for (int c = 0; c < 64; c++) {
                float p = __expf(srow[c] - mn);
                srow[c] = p;
                ls += p;
            }
            mrow[tid] = mn;
            lrow[tid] = lrow[tid] * al + ls;
            arow[tid] = al;
        }
        __syncthreads();

        // O = O*alpha + P @ V
        #pragma unroll
        for (int i = 0; i < 4; i++) {
            float al = arow[ty * 4 + i];
            #pragma unroll
            for (int j = 0; j < 4; j++) o[i][j] *= al;
        }
        #pragma unroll 8
        for (int k = 0; k < 64; k++) {
            float p[4], v[4];
            #pragma unroll
            for (int i = 0; i < 4; i++) p[i] = Ss[(ty * 4 + i) * ATTN_PAD + k];
            #pragma unroll
            for (int j = 0; j < 4; j++) v[j] = Vs[k * ATTN_PAD + tx * 4 + j];
            #pragma unroll
            for (int i = 0; i < 4; i++)
                #pragma unroll
                for (int j = 0; j < 4; j++)
                    o[i][j] = fmaf(p[i], v[j], o[i][j]);
        }
    }

    // write: Out[(b*SEQ + n)*DIM + h*HDIM + c], heads merged
    int b = bh >> 4, h = bh & 15;
    #pragma unroll
    for (int i = 0; i < 4; i++) {
        int r = ty * 4 + i;
        int n = q0 + r;
        float inv = 1.0f / lrow[r];
        #pragma unroll
        for (int j = 0; j < 4; j++) {
            int c = tx * 4 + j;
            Out[((size_t)b * SEQ + n) * DIM + h * HDIM + c] = o[i][j] * inv;
        }
    }
}

// ---------------- launch ----------------
extern "C" void kernel_launch(void* const* d_in, const int* in_sizes, int n_in,
                              void* d_out, int out_size)
{
    const float* z        = (const float*)d_in[0];
    const float* ln_scale = (const float*)d_in[1];
    const float* ln_bias  = (const float*)d_in[2];
    const float* w_qkv    = (const float*)d_in[3];
    const float* w_proj   = (const float*)d_in[4];
    const float* b_proj   = (const float*)d_in[5];
    float* out = (float*)d_out;

    float *zn, *att;
    cudaGetSymbolAddress((void**)&zn,  g_zn);
    cudaGetSymbolAddress((void**)&att, g_att);

    // 1) LayerNorm
    ln_kernel<<<ROWS, 256>>>(z, ln_scale, ln_bias, zn);

    // 2) QKV GEMM [4096,1024]@[1024,3072] with de-interleave scatter epilogue
    sgemm_kernel<0><<<dim3(QKVN / 128, ROWS / 128), 256>>>(
        zn, w_qkv, nullptr, nullptr, nullptr, ROWS, QKVN, DIM);

    // 3) attention (flash-style, fp32)
    static const int attn_smem = ATTN_SMEM_FLOATS * sizeof(float);
    cudaFuncSetAttribute(attn_kernel,
                         cudaFuncAttributeMaxDynamicSharedMemorySize, attn_smem);
    attn_kernel<<<dim3(SEQ / 64, BATCH * HEADS), 256, attn_smem>>>(att);

    // 4) output projection + bias + residual
    sgemm_kernel<1><<<dim3(DIM / 128, ROWS / 128), 256>>>(
        att, w_proj, out, z, b_proj, ROWS, DIM, DIM);
}

// round 2
// speedup vs baseline: 1.2516x; 1.2516x over previous
#include <cuda_runtime.h>
#include <math.h>
#include <stdint.h>

#define BATCH 2
#define SEQ   2048
#define DIM   1024
#define HEADS 16
#define HDIM  64
#define ROWS  (BATCH * SEQ)      // 4096
#define QKVN  (3 * DIM)          // 3072
#define EPS   1e-5f
#define INV_SCALE 0.125f         // 1/sqrt(64)

// ---------------- scratch (__device__ globals: no allocation allowed) --------
__device__ float g_zn [ROWS * DIM];
__device__ float g_q  [ROWS * DIM];   // [B*H, N, HD]
__device__ float g_k  [ROWS * DIM];
__device__ float g_v  [ROWS * DIM];
__device__ float g_att[ROWS * DIM];   // attention out [4096,1024]

// ---------------- tf32 helpers ----------------
__device__ __forceinline__ uint32_t f2tf(float x) {
    uint32_t r;
    asm("cvt.rna.tf32.f32 %0, %1;" : "=r"(r) : "f"(x));
    return r;
}
__device__ __forceinline__ void cvt2(float x, uint32_t& h, uint32_t& l) {
    h = f2tf(x);
    l = f2tf(x - __uint_as_float(h));
}
// D += A(16x8) * B(8x8), tf32 in, fp32 accum
__device__ __forceinline__ void mma8(float* c, const uint32_t* a, uint32_t b0, uint32_t b1) {
    asm volatile(
        "mma.sync.aligned.m16n8k8.row.col.f32.tf32.tf32.f32 "
        "{%0,%1,%2,%3}, {%4,%5,%6,%7}, {%8,%9}, {%0,%1,%2,%3};"
        : "+f"(c[0]), "+f"(c[1]), "+f"(c[2]), "+f"(c[3])
        : "r"(a[0]), "r"(a[1]), "r"(a[2]), "r"(a[3]), "r"(b0), "r"(b1));
}

// ---------------- LayerNorm ----------------
__global__ __launch_bounds__(256) void ln_kernel(
    const float* __restrict__ z, const float* __restrict__ sc,
    const float* __restrict__ bi, float* __restrict__ out)
{
    int row = blockIdx.x;
    int t = threadIdx.x;
    const float4 v = ((const float4*)(z + row * DIM))[t];
    float s  = v.x + v.y + v.z + v.w;
    float s2 = v.x*v.x + v.y*v.y + v.z*v.z + v.w*v.w;

    __shared__ float ssum[8], ssum2[8], stats[2];
    #pragma unroll
    for (int off = 16; off > 0; off >>= 1) {
        s  += __shfl_down_sync(0xffffffffu, s,  off);
        s2 += __shfl_down_sync(0xffffffffu, s2, off);
    }
    int lane = t & 31, wid = t >> 5;
    if (lane == 0) { ssum[wid] = s; ssum2[wid] = s2; }
    __syncthreads();
    if (t == 0) {
        float a = 0.f, b = 0.f;
        #pragma unroll
        for (int i = 0; i < 8; i++) { a += ssum[i]; b += ssum2[i]; }
        float mu  = a * (1.0f / DIM);
        float var = b * (1.0f / DIM) - mu * mu;
        stats[0] = mu;
        stats[1] = rsqrtf(var + EPS);
    }
    __syncthreads();
    float mu = stats[0], rstd = stats[1];
    float4 s4 = ((const float4*)sc)[t];
    float4 b4 = ((const float4*)bi)[t];
    float4 r;
    r.x = (v.x - mu) * rstd * s4.x + b4.x;
    r.y = (v.y - mu) * rstd * s4.y + b4.y;
    r.z = (v.z - mu) * rstd * s4.z + b4.z;
    r.w = (v.w - mu) * rstd * s4.w + b4.w;
    ((float4*)(out + row * DIM))[t] = r;
}

// ---------------- tf32x3 GEMM: 128x128 tile, kstep 32, 8 warps (2x4) --------
// MODE 0: C = A@B, scatter into g_q/g_k/g_v.  MODE 1: C = A@B + bias + zres.
#define GA_PAD 36
#define GB_PAD 136
#define GEMM_SMEM_BYTES ((2 * 128 * GA_PAD + 2 * 32 * GB_PAD) * 4)

template<int MODE>
__global__ __launch_bounds__(256) void gemm_tf32(
    const float* __restrict__ A, const float* __restrict__ B,
    float* __restrict__ C, const float* __restrict__ zres,
    const float* __restrict__ bias, int M, int Ncols, int K)
{
    extern __shared__ uint32_t smg[];
    uint32_t* Ah = smg;
    uint32_t* Al = Ah + 128 * GA_PAD;
    uint32_t* Bh = Al + 128 * GA_PAD;
    uint32_t* Bl = Bh + 32 * GB_PAD;

    int tid = threadIdx.x;
    int wid = tid >> 5, lane = tid & 31;
    int wm = wid >> 2, wn = wid & 3;      // warp grid 2x4
    int g = lane >> 2, qd = lane & 3;
    int bm = blockIdx.y * 128, bn = blockIdx.x * 128;

    float acc[4][4][4] = {};

    for (int kk = 0; kk < K; kk += 32) {
        // load + convert A tile (128x32)
        #pragma unroll
        for (int i = 0; i < 4; i++) {
            int r = (tid >> 3) + 32 * i;
            int c = (tid & 7) * 4;
            float4 v = *(const float4*)(A + (size_t)(bm + r) * K + kk + c);
            uint32_t h, l;
            cvt2(v.x, h, l); Ah[r*GA_PAD+c  ] = h; Al[r*GA_PAD+c  ] = l;
            cvt2(v.y, h, l); Ah[r*GA_PAD+c+1] = h; Al[r*GA_PAD+c+1] = l;
            cvt2(v.z, h, l); Ah[r*GA_PAD+c+2] = h; Al[r*GA_PAD+c+2] = l;
            cvt2(v.w, h, l); Ah[r*GA_PAD+c+3] = h; Al[r*GA_PAD+c+3] = l;
        }
        // load + convert B tile (32x128)
        {
            int r = tid >> 3;
            #pragma unroll
            for (int i = 0; i < 4; i++) {
                int c = (tid & 7) * 16 + i * 4;
                float4 v = *(const float4*)(B + (size_t)(kk + r) * Ncols + bn + c);
                uint32_t h, l;
                cvt2(v.x, h, l); Bh[r*GB_PAD+c  ] = h; Bl[r*GB_PAD+c  ] = l;
                cvt2(v.y, h, l); Bh[r*GB_PAD+c+1] = h; Bl[r*GB_PAD+c+1] = l;
                cvt2(v.z, h, l); Bh[r*GB_PAD+c+2] = h; Bl[r*GB_PAD+c+2] = l;
                cvt2(v.w, h, l); Bh[r*GB_PAD+c+3] = h; Bl[r*GB_PAD+c+3] = l;
            }
        }
        __syncthreads();

        #pragma unroll
        for (int ks = 0; ks < 4; ks++) {
            int k8 = ks * 8;
            uint32_t ah[4][4], al_[4][4];
            #pragma unroll
            for (int mi = 0; mi < 4; mi++) {
                int base = (64*wm + 16*mi + g) * GA_PAD + k8 + qd;
                ah [mi][0] = Ah[base];              ah [mi][1] = Ah[base + 8*GA_PAD];
                ah [mi][2] = Ah[base + 4];          ah [mi][3] = Ah[base + 8*GA_PAD + 4];
                al_[mi][0] = Al[base];              al_[mi][1] = Al[base + 8*GA_PAD];
                al_[mi][2] = Al[base + 4];          al_[mi][3] = Al[base + 8*GA_PAD + 4];
            }
            uint32_t bh[4][2], bl[4][2];
            #pragma unroll
            for (int ni = 0; ni < 4; ni++) {
                int base = (k8 + qd) * GB_PAD + 32*wn + 8*ni + g;
                bh[ni][0] = Bh[base]; bh[ni][1] = Bh[base + 4*GB_PAD];
                bl[ni][0] = Bl[base]; bl[ni][1] = Bl[base + 4*GB_PAD];
            }
            #pragma unroll
            for (int mi = 0; mi < 4; mi++)
                #pragma unroll
                for (int ni = 0; ni < 4; ni++) {
                    mma8(acc[mi][ni], ah[mi],  bh[ni][0], bh[ni][1]);
                    mma8(acc[mi][ni], al_[mi], bh[ni][0], bh[ni][1]);
                    mma8(acc[mi][ni], ah[mi],  bl[ni][0], bl[ni][1]);
                }
        }
        __syncthreads();
    }

    // epilogue
    #pragma unroll
    for (int mi = 0; mi < 4; mi++)
        #pragma unroll
        for (int ni = 0; ni < 4; ni++)
            #pragma unroll
            for (int j = 0; j < 4; j++) {
                int gm = bm + 64*wm + 16*mi + g + ((j >> 1) << 3);
                int gn = bn + 32*wn + 8*ni + 2*qd + (j & 1);
                if (MODE == 0) {
                    int bb = gm >> 11;
                    int nn = gm & (SEQ - 1);
                    int h   = gn / 192;
                    int rem = gn - h * 192;
                    int d   = rem / 3;
                    int w   = rem - d * 3;
                    float* dst = (w == 0) ? g_q : (w == 1) ? g_k : g_v;
                    dst[(((size_t)bb * HEADS + h) * SEQ + nn) * HDIM + d] = acc[mi][ni][j];
                } else {
                    size_t idx = (size_t)gm * Ncols + gn;
                    C[idx] = acc[mi][ni][j] + bias[gn] + zres[idx];
                }
            }
}

// ---------------- tf32x3 flash attention ----------------
// block = 256 thr (8 warps), tile: 128 q-rows x 64 k-cols, HD=64.
// warp w owns q-rows [16w, 16w+16).
#define QP 68
#define KP 72
#define ATTN_SMEM_BYTES ((2*128*QP + 4*64*KP + 2*128*QP) * 4)   // 212992

__global__ __launch_bounds__(256) void attn_tf32(float* __restrict__ Out)
{
    extern __shared__ uint32_t sma[];
    uint32_t* Qh = sma;
    uint32_t* Ql = Qh + 128 * QP;
    uint32_t* Kh = Ql + 128 * QP;
    uint32_t* Kl = Kh + 64 * KP;
    uint32_t* Vh = Kl + 64 * KP;
    uint32_t* Vl = Vh + 64 * KP;
    uint32_t* Ph = Vl + 64 * KP;
    uint32_t* Pl = Ph + 128 * QP;

    int tid = threadIdx.x;
    int wid = tid >> 5, lane = tid & 31;
    int g = lane >> 2, qd = lane & 3;
    int bh = blockIdx.y;
    int q0 = blockIdx.x * 128;
    int mrow = wid * 16;

    const float* Qb = g_q + ((size_t)bh * SEQ + q0) * HDIM;
    #pragma unroll
    for (int j = 0; j < 8; j++) {
        int idx = tid + 256 * j;
        int r = idx >> 4, c = (idx & 15) * 4;
        float4 v = *(const float4*)(Qb + r * 64 + c);
        uint32_t h, l;
        cvt2(v.x, h, l); Qh[r*QP+c  ] = h; Ql[r*QP+c  ] = l;
        cvt2(v.y, h, l); Qh[r*QP+c+1] = h; Ql[r*QP+c+1] = l;
        cvt2(v.z, h, l); Qh[r*QP+c+2] = h; Ql[r*QP+c+2] = l;
        cvt2(v.w, h, l); Qh[r*QP+c+3] = h; Ql[r*QP+c+3] = l;
    }

    float o[8][4] = {};
    float m0 = -1e30f, m1 = -1e30f, l0 = 0.f, l1 = 0.f;

    for (int kt = 0; kt < SEQ / 64; kt++) {
        __syncthreads();   // prior PV readers of K/V/P done
        const float* Kb = g_k + ((size_t)bh * SEQ + kt * 64) * HDIM;
        const float* Vb = g_v + ((size_t)bh * SEQ + kt * 64) * HDIM;
        #pragma unroll
        for (int j = 0; j < 4; j++) {
            int idx = tid + 256 * j;
            int r = idx >> 4, c = (idx & 15) * 4;
            float4 kv = *(const float4*)(Kb + r * 64 + c);
            float4 vv = *(const float4*)(Vb + r * 64 + c);
            uint32_t h, l;
            cvt2(kv.x, h, l); Kh[r*KP+c  ] = h; Kl[r*KP+c  ] = l;
            cvt2(kv.y, h, l); Kh[r*KP+c+1] = h; Kl[r*KP+c+1] = l;
            cvt2(kv.z, h, l); Kh[r*KP+c+2] = h; Kl[r*KP+c+2] = l;
            cvt2(kv.w, h, l); Kh[r*KP+c+3] = h; Kl[r*KP+c+3] = l;
            cvt2(vv.x, h, l); Vh[r*KP+c  ] = h; Vl[r*KP+c  ] = l;
            cvt2(vv.y, h, l); Vh[r*KP+c+1] = h; Vl[r*KP+c+1] = l;
            cvt2(vv.z, h, l); Vh[r*KP+c+2] = h; Vl[r*KP+c+2] = l;
            cvt2(vv.w, h, l); Vh[r*KP+c+3] = h; Vl[r*KP+c+3] = l;
        }
        __syncthreads();

        // S = Q @ K^T  (16 x 64 per warp)
        float s[8][4] = {};
        #pragma unroll
        for (int k8 = 0; k8 < 64; k8 += 8) {
            uint32_t ah[4], al_[4];
            int abase = (mrow + g) * QP + k8 + qd;
            ah [0] = Qh[abase];          ah [1] = Qh[abase + 8*QP];
            ah [2] = Qh[abase + 4];      ah [3] = Qh[abase + 8*QP + 4];
            al_[0] = Ql[abase];          al_[1] = Ql[abase + 8*QP];
            al_[2] = Ql[abase + 4];      al_[3] = Ql[abase + 8*QP + 4];
            #pragma unroll
            for (int ni = 0; ni < 8; ni++) {
                int bbase = (8*ni + g) * KP + k8 + qd;
                uint32_t b0h = Kh[bbase], b1h = Kh[bbase + 4];
                uint32_t b0l = Kl[bbase], b1l = Kl[bbase + 4];
                mma8(s[ni], ah,  b0h, b1h);
                mma8(s[ni], al_, b0h, b1h);
                mma8(s[ni], ah,  b0l, b1l);
            }
        }
        #pragma unroll
        for (int ni = 0; ni < 8; ni++)
            #pragma unroll
            for (int j = 0; j < 4; j++) s[ni][j] *= INV_SCALE;

        // online softmax (rows g and g+8 of this warp's 16)
        float t0 = -1e30f, t1 = -1e30f;
        #pragma unroll
        for (int ni = 0; ni < 8; ni++) {
            t0 = fmaxf(t0, fmaxf(s[ni][0], s[ni][1]));
            t1 = fmaxf(t1, fmaxf(s[ni][2], s[ni][3]));
        }
        t0 = fmaxf(t0, __shfl_xor_sync(0xffffffffu, t0, 1));
        t0 = fmaxf(t0, __shfl_xor_sync(0xffffffffu, t0, 2));
        t1 = fmaxf(t1, __shfl_xor_sync(0xffffffffu, t1, 1));
        t1 = fmaxf(t1, __shfl_xor_sync(0xffffffffu, t1, 2));
        float mn0 = fmaxf(m0, t0), mn1 = fmaxf(m1, t1);
        float a0 = __expf(m0 - mn0), a1 = __expf(m1 - mn1);
        m0 = mn0; m1 = mn1;
        float p0 = 0.f, p1 = 0.f;
        #pragma unroll
        for (int ni = 0; ni < 8; ni++) {
            s[ni][0] = __expf(s[ni][0] - mn0); p0 += s[ni][0];
            s[ni][1] = __expf(s[ni][1] - mn0); p0 += s[ni][1];
            s[ni][2] = __expf(s[ni][2] - mn1); p1 += s[ni][2];
            s[ni][3] = __expf(s[ni][3] - mn1); p1 += s[ni][3];
        }
        p0 += __shfl_xor_sync(0xffffffffu, p0, 1);
        p0 += __shfl_xor_sync(0xffffffffu, p0, 2);
        p1 += __shfl_xor_sync(0xffffffffu, p1, 1);
        p1 += __shfl_xor_sync(0xffffffffu, p1, 2);
        l0 = l0 * a0 + p0;
        l1 = l1 * a1 + p1;
        #pragma unroll
        for (int ni = 0; ni < 8; ni++) {
            o[ni][0] *= a0; o[ni][1] *= a0;
            o[ni][2] *= a1; o[ni][3] *= a1;
        }

        // write P (hi/lo) to smem for PV A-fragments
        #pragma unroll
        for (int ni = 0; ni < 8; ni++) {
            int r0 = mrow + g;
            int col = 8*ni + 2*qd;
            uint32_t h, l;
            cvt2(s[ni][0], h, l); Ph[r0*QP + col    ] = h; Pl[r0*QP + col    ] = l;
            cvt2(s[ni][1], h, l); Ph[r0*QP + col + 1] = h; Pl[r0*QP + col + 1] = l;
            cvt2(s[ni][2], h, l); Ph[(r0+8)*QP + col    ] = h; Pl[(r0+8)*QP + col    ] = l;
            cvt2(s[ni][3], h, l); Ph[(r0+8)*QP + col + 1] = h; Pl[(r0+8)*QP + col + 1] = l;
        }
        __syncthreads();

        // O += P @ V
        #pragma unroll
        for (int k8 = 0; k8 < 64; k8 += 8) {
            uint32_t ah[4], al_[4];
            int abase = (mrow + g) * QP + k8 + qd;
            ah [0] = Ph[abase];          ah [1] = Ph[abase + 8*QP];
            ah [2] = Ph[abase + 4];      ah [3] = Ph[abase + 8*QP + 4];
            al_[0] = Pl[abase];          al_[1] = Pl[abase + 8*QP];
            al_[2] = Pl[abase + 4];      al_[3] = Pl[abase + 8*QP + 4];
            #pragma unroll
            for (int ni = 0; ni < 8; ni++) {
                int bbase = (k8 + qd) * KP + 8*ni + g;
                uint32_t b0h = Vh[bbase], b1h = Vh[bbase + 4*KP];
                uint32_t b0l = Vl[bbase], b1l = Vl[bbase + 4*KP];
                mma8(o[ni], ah,  b0h, b1h);
                mma8(o[ni], al_, b0h, b1h);
                mma8(o[ni], ah,  b0l, b1l);
            }
        }
    }

    // final: divide by l, write merged-head layout
    float inv0 = 1.f / l0, inv1 = 1.f / l1;
    int b = bh >> 4, h = bh & 15;
    int n0 = q0 + mrow + g;
    #pragma unroll
    for (int ni = 0; ni < 8; ni++) {
        int col = h * HDIM + 8*ni + 2*qd;
        Out[((size_t)b * SEQ + n0) * DIM + col    ] = o[ni][0] * inv0;
        Out[((size_t)b * SEQ + n0) * DIM + col + 1] = o[ni][1] * inv0;
        Out[((size_t)b * SEQ + n0 + 8) * DIM + col    ] = o[ni][2] * inv1;
        Out[((size_t)b * SEQ + n0 + 8) * DIM + col + 1] = o[ni][3] * inv1;
    }
}

// ---------------- launch ----------------
extern "C" void kernel_launch(void* const* d_in, const int* in_sizes, int n_in,
                              void* d_out, int out_size)
{
    const float* z        = (const float*)d_in[0];
    const float* ln_scale = (const float*)d_in[1];
    const float* ln_bias  = (const float*)d_in[2];
    const float* w_qkv    = (const float*)d_in[3];
    const float* w_proj   = (const float*)d_in[4];
    const float* b_proj   = (const float*)d_in[5];
    float* out = (float*)d_out;

    float *zn, *att;
    cudaGetSymbolAddress((void**)&zn,  g_zn);
    cudaGetSymbolAddress((void**)&att, g_att);

    cudaFuncSetAttribute(gemm_tf32<0>, cudaFuncAttributeMaxDynamicSharedMemorySize, GEMM_SMEM_BYTES);
    cudaFuncSetAttribute(gemm_tf32<1>, cudaFuncAttributeMaxDynamicSharedMemorySize, GEMM_SMEM_BYTES);
    cudaFuncSetAttribute(attn_tf32,    cudaFuncAttributeMaxDynamicSharedMemorySize, ATTN_SMEM_BYTES);

    // 1) LayerNorm
    ln_kernel<<<ROWS, 256>>>(z, ln_scale, ln_bias, zn);

    // 2) QKV GEMM with de-interleave scatter epilogue
    gemm_tf32<0><<<dim3(QKVN / 128, ROWS / 128), 256, GEMM_SMEM_BYTES>>>(
        zn, w_qkv, nullptr, nullptr, nullptr, ROWS, QKVN, DIM);

    // 3) attention (tf32x3 flash)
    attn_tf32<<<dim3(SEQ / 128, BATCH * HEADS), 256, ATTN_SMEM_BYTES>>>(att);

    // 4) output projection + bias + residual
    gemm_tf32<1><<<dim3(DIM / 128, ROWS / 128), 256, GEMM_SMEM_BYTES>>>(
        att, w_proj, out, z, b_proj, ROWS, DIM, DIM);
}